// round 2
// baseline (speedup 1.0000x reference)
#include <cuda_runtime.h>
#include <cuda_bf16.h>
#include <math.h>

// ---------------------------------------------------------------------------
// SpatialPatchMoE:  x [2,64,8,128,128] fp32, P=8 -> 512 patches, top-2 of 8
// experts. out = residual + sum_{top2} w_e * GatedConvBlock_e(patch).
// (softmaxed top-k weights sum to 1, so the dense 8-expert loop in the
//  reference collapses to 2 experts + residual.)
// ---------------------------------------------------------------------------

#define NPATCH 512
#define CCH    64
#define LDEP   8
#define PLANE  16384          // 128*128
#define EPS    1e-5f

// router results
__device__ int2   g_topi[NPATCH];
__device__ float2 g_topw[NPATCH];

// ---------------------------------------------------------------------------
// Router: per-patch channel means -> logits -> top2 -> softmax(2)
// ---------------------------------------------------------------------------
__global__ void router_kernel(const float* __restrict__ x,
                              const float* __restrict__ rw,
                              const float* __restrict__ rb)
{
    __shared__ float part[512];
    __shared__ float meanv[64];
    __shared__ float logits[8];

    int n = blockIdx.x;
    int b = n >> 8, rem = n & 255, ph = rem >> 4, pw_ = rem & 15;
    const float* xb = x + ((size_t)b * CCH * LDEP) * PLANE + (ph * 8) * 128 + pw_ * 8;
    int t = threadIdx.x;

    for (int i = t; i < 512; i += 256) {
        int c = i >> 3, l = i & 7;
        const float* p0 = xb + ((size_t)c * LDEP + l) * PLANE;
        float s = 0.f;
        #pragma unroll
        for (int p = 0; p < 8; ++p) {
            const float* r = p0 + p * 128;
            #pragma unroll
            for (int q = 0; q < 8; ++q) s += r[q];
        }
        part[i] = s;
    }
    __syncthreads();
    if (t < 64) {
        float s = 0.f;
        #pragma unroll
        for (int l = 0; l < 8; ++l) s += part[t * 8 + l];
        meanv[t] = s * (1.f / 512.f);
    }
    __syncthreads();
    if (t < 8) {
        float s = rb[t];
        #pragma unroll 8
        for (int c = 0; c < 64; ++c) s += meanv[c] * rw[t * 64 + c];
        logits[t] = s;
    }
    __syncthreads();
    if (t == 0) {
        int i1 = 0; float v1 = logits[0];
        #pragma unroll
        for (int e = 1; e < 8; ++e)
            if (logits[e] > v1) { v1 = logits[e]; i1 = e; }
        int i2 = -1; float v2 = -1e30f;
        #pragma unroll
        for (int e = 0; e < 8; ++e) {
            if (e == i1) continue;
            if (logits[e] > v2) { v2 = logits[e]; i2 = e; }
        }
        float e2 = expf(v2 - v1);
        float inv = 1.f / (1.f + e2);
        g_topi[n] = make_int2(i1, i2);
        g_topw[n] = make_float2(inv, e2 * inv);
    }
}

// ---------------------------------------------------------------------------
// Fused expert kernel: one CTA per (patch, l). 256 threads.
// smem layout (floats):
//   xs   [64*65]  x tile (stride 65: conflict-free scalar access)
//   hs   [64*68]  LN output, then reused for gated values (stride 68:
//                 conflict-free STS.128 / LDS.128)
//   wdw  [64*49], lnw[64], lnb[64]
//   win  [128*65], bin[128], wout[64*65], bout[64]
//   red  [512], stat[128]
// ---------------------------------------------------------------------------
#define OFF_XS    0
#define OFF_HS    4160
#define OFF_WDW   8512
#define OFF_LNW   11648
#define OFF_LNB   11712
#define OFF_WIN   11776
#define OFF_BIN   20096
#define OFF_WOUT  20224
#define OFF_BOUT  24384
#define OFF_RED   24448
#define OFF_STAT  24960
#define SMEM_FLOATS 25088
#define SMEM_BYTES  (SMEM_FLOATS * 4)

__global__ void __launch_bounds__(256, 2)
moe_kernel(const float* __restrict__ x,
           const float* __restrict__ dw_w,
           const float* __restrict__ ln_w,  const float* __restrict__ ln_b,
           const float* __restrict__ pw_in_w,  const float* __restrict__ pw_in_b,
           const float* __restrict__ pw_out_w, const float* __restrict__ pw_out_b,
           float* __restrict__ out)
{
    extern __shared__ float sm[];
    float* xs   = sm + OFF_XS;
    float* hs   = sm + OFF_HS;
    float* wdw  = sm + OFF_WDW;
    float* lnw  = sm + OFF_LNW;
    float* lnb  = sm + OFF_LNB;
    float* win  = sm + OFF_WIN;
    float* bin  = sm + OFF_BIN;
    float* wout = sm + OFF_WOUT;
    float* bout = sm + OFF_BOUT;
    float* red  = sm + OFF_RED;
    float* stat = sm + OFF_STAT;

    int unit = blockIdx.x;
    int n = unit >> 3, l = unit & 7;
    int b = n >> 8, rem = n & 255, ph = rem >> 4, pw_ = rem & 15;
    const size_t cstride = (size_t)LDEP * PLANE;  // per-channel stride
    const float* xbase = x + ((size_t)b * CCH * LDEP + l) * PLANE
                           + (ph * 8) * 128 + pw_ * 8;
    int t = threadIdx.x;

    // ---- load x tile ----
    for (int i = t; i < 4096; i += 256) {
        int c = i >> 6, j = i & 63, p = (j >> 3), q = j & 7;
        xs[c * 65 + j] = xbase[(size_t)c * cstride + p * 128 + q];
    }

    int2   ei = g_topi[n];
    float2 ew = g_topw[n];

    int c_ = t & 63, k4 = t >> 6;     // conv/LN mapping (warp-uniform k4)
    int jt = t & 15, ot = t >> 4;     // gemm mapping
    int j0 = jt * 4;

    __syncthreads();

    // residual in registers
    float oacc[4][4];
    #pragma unroll
    for (int m = 0; m < 4; ++m) {
        int o = ot + m * 16;
        #pragma unroll
        for (int r = 0; r < 4; ++r) oacc[m][r] = xs[o * 65 + j0 + r];
    }

    for (int kk = 0; kk < 2; ++kk) {
        int   e    = kk ? ei.y : ei.x;
        float wexp = kk ? ew.y : ew.x;

        __syncthreads();  // prior-expert reads of weights/hs are done

        // ---- stage expert weights ----
        {
            const float* g = dw_w + (size_t)e * 3136;
            for (int i = t; i < 3136; i += 256) wdw[i] = g[i];
            if (t < 64) { lnw[t] = ln_w[e * 64 + t]; lnb[t] = ln_b[e * 64 + t]; }
            const float* gi = pw_in_w + (size_t)e * 8192;
            for (int i = t; i < 8192; i += 256) {
                int o = i >> 6, c = i & 63;
                win[o * 65 + c] = gi[i];
            }
            if (t < 128) bin[t] = pw_in_b[e * 128 + t];
            const float* go = pw_out_w + (size_t)e * 4096;
            for (int i = t; i < 4096; i += 256) {
                int o = i >> 6, c = i & 63;
                wout[o * 65 + c] = go[i];
            }
            if (t < 64) bout[t] = pw_out_b[e * 64 + t];
        }
        __syncthreads();

        // ---- depthwise 7x7 conv (zero-padded within the 8x8 patch) ----
        // (dw_b is constant per channel -> cancels exactly in the LayerNorm)
        float hv[16];
        {
            const float* xr = xs + c_ * 65;
            const float* wr = wdw + c_ * 49;
            int pbase = k4 * 2;
            #pragma unroll
            for (int jj = 0; jj < 16; ++jj) {
                int p = pbase + (jj >> 3);
                int q = jj & 7;
                float acc = 0.f;
                for (int dp = 0; dp < 7; ++dp) {
                    int pp = p + dp - 3;
                    if ((unsigned)pp > 7u) continue;
                    const float* xrow = xr + pp * 8;
                    const float* wrow = wr + dp * 7;
                    #pragma unroll
                    for (int dq = 0; dq < 7; ++dq) {
                        int qq = q + dq - 3;
                        if ((unsigned)qq > 7u) continue;
                        acc = fmaf(xrow[qq], wrow[dq], acc);
                    }
                }
                hv[jj] = acc;
            }
        }

        // ---- LayerNorm over the 64 spatial positions of each (c) ----
        {
            float s = 0.f, sq = 0.f;
            #pragma unroll
            for (int jj = 0; jj < 16; ++jj) { s += hv[jj]; sq += hv[jj] * hv[jj]; }
            red[t] = s; red[256 + t] = sq;
        }
        __syncthreads();
        if (t < 64) {
            float S = red[t] + red[t + 64] + red[t + 128] + red[t + 192];
            float Q = red[256 + t] + red[320 + t] + red[384 + t] + red[448 + t];
            float mu  = S * (1.f / 64.f);
            float var = fmaxf(Q * (1.f / 64.f) - mu * mu, 0.f);
            stat[t]      = mu;
            stat[64 + t] = rsqrtf(var + EPS);
        }
        __syncthreads();
        {
            float mu = stat[c_], rs = stat[64 + c_];
            float* hrow = hs + c_ * 68 + k4 * 16;
            #pragma unroll
            for (int v = 0; v < 4; ++v) {
                int j = k4 * 16 + v * 4;
                float4 o4;
                o4.x = (hv[v*4+0] - mu) * rs * lnw[j+0] + lnb[j+0];
                o4.y = (hv[v*4+1] - mu) * rs * lnw[j+1] + lnb[j+1];
                o4.z = (hv[v*4+2] - mu) * rs * lnw[j+2] + lnb[j+2];
                o4.w = (hv[v*4+3] - mu) * rs * lnw[j+3] + lnb[j+3];
                *(float4*)(hrow + v * 4) = o4;
            }
        }
        __syncthreads();

        // ---- pw_in: [128,64] @ [64,64pos] with register tiles ----
        float fa[4][4] = {}, fg[4][4] = {};
        #pragma unroll 4
        for (int c = 0; c < 64; ++c) {
            float4 h4 = *(const float4*)(hs + c * 68 + j0);
            #pragma unroll
            for (int m = 0; m < 4; ++m) {
                int oa = ot + m * 16;
                float wa = win[oa * 65 + c];
                float wg = win[(oa + 64) * 65 + c];
                fa[m][0] = fmaf(wa, h4.x, fa[m][0]);
                fa[m][1] = fmaf(wa, h4.y, fa[m][1]);
                fa[m][2] = fmaf(wa, h4.z, fa[m][2]);
                fa[m][3] = fmaf(wa, h4.w, fa[m][3]);
                fg[m][0] = fmaf(wg, h4.x, fg[m][0]);
                fg[m][1] = fmaf(wg, h4.y, fg[m][1]);
                fg[m][2] = fmaf(wg, h4.z, fg[m][2]);
                fg[m][3] = fmaf(wg, h4.w, fg[m][3]);
            }
        }
        __syncthreads();  // all reads of hs finished

        // ---- gate: silu(a) * g, write back into hs ----
        #pragma unroll
        for (int m = 0; m < 4; ++m) {
            int oa = ot + m * 16;
            float ba = bin[oa], bg = bin[oa + 64];
            float4 gv;
            {
                float a = fa[m][0] + ba, g = fg[m][0] + bg;
                gv.x = a * g * __fdividef(1.f, 1.f + __expf(-a));
                a = fa[m][1] + ba; g = fg[m][1] + bg;
                gv.y = a * g * __fdividef(1.f, 1.f + __expf(-a));
                a = fa[m][2] + ba; g = fg[m][2] + bg;
                gv.z = a * g * __fdividef(1.f, 1.f + __expf(-a));
                a = fa[m][3] + ba; g = fg[m][3] + bg;
                gv.w = a * g * __fdividef(1.f, 1.f + __expf(-a));
            }
            *(float4*)(hs + oa * 68 + j0) = gv;
        }
        __syncthreads();

        // ---- pw_out: [64,64] @ [64,64pos] ----
        float ro[4][4] = {};
        #pragma unroll 4
        for (int c = 0; c < 64; ++c) {
            float4 g4 = *(const float4*)(hs + c * 68 + j0);
            #pragma unroll
            for (int m = 0; m < 4; ++m) {
                float w = wout[(ot + m * 16) * 65 + c];
                ro[m][0] = fmaf(w, g4.x, ro[m][0]);
                ro[m][1] = fmaf(w, g4.y, ro[m][1]);
                ro[m][2] = fmaf(w, g4.z, ro[m][2]);
                ro[m][3] = fmaf(w, g4.w, ro[m][3]);
            }
        }
        #pragma unroll
        for (int m = 0; m < 4; ++m) {
            int o = ot + m * 16;
            float bo = bout[o];
            #pragma unroll
            for (int r = 0; r < 4; ++r)
                oacc[m][r] = fmaf(wexp, ro[m][r] + bo, oacc[m][r]);
        }
    }

    // ---- write out (vectorized, coalesced within 32B rows) ----
    float* obase = out + ((size_t)b * CCH * LDEP + l) * PLANE
                       + (ph * 8) * 128 + pw_ * 8;
    int p = j0 >> 3, q = j0 & 7;
    #pragma unroll
    for (int m = 0; m < 4; ++m) {
        int o = ot + m * 16;
        float4 v = make_float4(oacc[m][0], oacc[m][1], oacc[m][2], oacc[m][3]);
        *(float4*)(obase + (size_t)o * cstride + p * 128 + q) = v;
    }
}

// ---------------------------------------------------------------------------
extern "C" void kernel_launch(void* const* d_in, const int* in_sizes, int n_in,
                              void* d_out, int out_size)
{
    const float* x        = (const float*)d_in[0];
    const float* router_w = (const float*)d_in[1];
    const float* router_b = (const float*)d_in[2];
    const float* dw_w     = (const float*)d_in[3];
    // d_in[4] = dw_b: constant per channel, cancels exactly through LayerNorm
    const float* ln_w     = (const float*)d_in[5];
    const float* ln_b     = (const float*)d_in[6];
    const float* pw_in_w  = (const float*)d_in[7];
    const float* pw_in_b  = (const float*)d_in[8];
    const float* pw_out_w = (const float*)d_in[9];
    const float* pw_out_b = (const float*)d_in[10];
    float* out = (float*)d_out;

    // Host-side, non-stream, idempotent: safe under graph capture, no static
    // guard needed.
    cudaFuncSetAttribute(moe_kernel,
                         cudaFuncAttributeMaxDynamicSharedMemorySize,
                         SMEM_BYTES);

    router_kernel<<<NPATCH, 256>>>(x, router_w, router_b);
    moe_kernel<<<NPATCH * LDEP, 256, SMEM_BYTES>>>(
        x, dw_w, ln_w, ln_b, pw_in_w, pw_in_b, pw_out_w, pw_out_b, out);
}

// round 4
// speedup vs baseline: 1.2084x; 1.2084x over previous
#include <cuda_runtime.h>
#include <cuda_bf16.h>
#include <math.h>

// ---------------------------------------------------------------------------
// SpatialPatchMoE:  x [2,64,8,128,128] fp32, P=8 -> 512 patches, top-2 of 8
// experts. out = residual + sum_{top2} w_e * GatedConvBlock_e(patch).
// ---------------------------------------------------------------------------

#define NPATCH 512
#define CCH    64
#define LDEP   8
#define PLANE  16384          // 128*128
#define EPS    1e-5f

__device__ int2   g_topi[NPATCH];
__device__ float2 g_topw[NPATCH];

// ---------------------------------------------------------------------------
// Router
// ---------------------------------------------------------------------------
__global__ void router_kernel(const float* __restrict__ x,
                              const float* __restrict__ rw,
                              const float* __restrict__ rb)
{
    __shared__ float part[512];
    __shared__ float meanv[64];
    __shared__ float logits[8];

    int n = blockIdx.x;
    int b = n >> 8, rem = n & 255, ph = rem >> 4, pw_ = rem & 15;
    const float* xb = x + ((size_t)b * CCH * LDEP) * PLANE + (ph * 8) * 128 + pw_ * 8;
    int t = threadIdx.x;

    for (int i = t; i < 512; i += 256) {
        int c = i >> 3, l = i & 7;
        const float* p0 = xb + ((size_t)c * LDEP + l) * PLANE;
        float s = 0.f;
        #pragma unroll
        for (int p = 0; p < 8; ++p) {
            const float* r = p0 + p * 128;
            #pragma unroll
            for (int q = 0; q < 8; ++q) s += r[q];
        }
        part[i] = s;
    }
    __syncthreads();
    if (t < 64) {
        float s = 0.f;
        #pragma unroll
        for (int l = 0; l < 8; ++l) s += part[t * 8 + l];
        meanv[t] = s * (1.f / 512.f);
    }
    __syncthreads();
    if (t < 8) {
        float s = rb[t];
        #pragma unroll 8
        for (int c = 0; c < 64; ++c) s += meanv[c] * rw[t * 64 + c];
        logits[t] = s;
    }
    __syncthreads();
    if (t == 0) {
        int i1 = 0; float v1 = logits[0];
        #pragma unroll
        for (int e = 1; e < 8; ++e)
            if (logits[e] > v1) { v1 = logits[e]; i1 = e; }
        int i2 = -1; float v2 = -1e30f;
        #pragma unroll
        for (int e = 0; e < 8; ++e) {
            if (e == i1) continue;
            if (logits[e] > v2) { v2 = logits[e]; i2 = e; }
        }
        float e2 = expf(v2 - v1);
        float inv = 1.f / (1.f + e2);
        g_topi[n] = make_int2(i1, i2);
        g_topw[n] = make_float2(inv, e2 * inv);
    }
}

// ---------------------------------------------------------------------------
// Register-tiled depthwise 7x7 conv over an 8x8 patch, output rows P0, P0+1.
// All padding predicates are compile-time; x rows loaded as float4 pairs.
// ---------------------------------------------------------------------------
template<int P0> __device__ __forceinline__
void conv_pair(const float* __restrict__ xr, const float* __restrict__ wr,
               float hv[16])
{
    #pragma unroll
    for (int i = 0; i < 16; ++i) hv[i] = 0.f;
    constexpr int ppLo = (P0 - 3 < 0) ? 0 : P0 - 3;
    constexpr int ppHi = (P0 + 4 > 7) ? 7 : P0 + 4;
    #pragma unroll
    for (int pp = ppLo; pp <= ppHi; ++pp) {
        float4 a  = *(const float4*)(xr + pp * 8);
        float4 bq = *(const float4*)(xr + pp * 8 + 4);
        float xrow[8] = {a.x, a.y, a.z, a.w, bq.x, bq.y, bq.z, bq.w};
        #pragma unroll
        for (int r = 0; r < 2; ++r) {
            const int dp = pp - (P0 + r) + 3;
            if (dp < 0 || dp > 6) continue;
            const float* wrow = wr + dp * 7;
            #pragma unroll
            for (int dq = 0; dq < 7; ++dq) {
                float wv = wrow[dq];
                #pragma unroll
                for (int q = 0; q < 8; ++q) {
                    int qq = q + dq - 3;
                    if (qq < 0 || qq > 7) continue;
                    hv[r * 8 + q] = fmaf(xrow[qq], wv, hv[r * 8 + q]);
                }
            }
        }
    }
}

#define ACC4(facc, wv, hh)                        \
    facc[0] = fmaf(wv, hh.x, facc[0]);            \
    facc[1] = fmaf(wv, hh.y, facc[1]);            \
    facc[2] = fmaf(wv, hh.z, facc[2]);            \
    facc[3] = fmaf(wv, hh.w, facc[3]);

// ---------------------------------------------------------------------------
// smem layout (floats) — all hot tiles at stride 68 (16B-aligned rows,
// conflict-free vector access)
// ---------------------------------------------------------------------------
#define OFF_XS    0        // 64*68 = 4352
#define OFF_HS    4352     // 64*68 = 4352
#define OFF_WDW   8704     // 3136
#define OFF_LNW   11840    // 64
#define OFF_LNB   11904    // 64
#define OFF_WIN   11968    // 128*68 = 8704
#define OFF_BIN   20672    // 128
#define OFF_WOUT  20800    // 64*68 = 4352
#define OFF_BOUT  25152    // 64
#define OFF_RED   25216    // 512
#define OFF_STAT  25728    // 128
#define SMEM_FLOATS 25856
#define SMEM_BYTES  (SMEM_FLOATS * 4)

__global__ void __launch_bounds__(256, 2)
moe_kernel(const float* __restrict__ x,
           const float* __restrict__ dw_w,
           const float* __restrict__ ln_w,  const float* __restrict__ ln_b,
           const float* __restrict__ pw_in_w,  const float* __restrict__ pw_in_b,
           const float* __restrict__ pw_out_w, const float* __restrict__ pw_out_b,
           float* __restrict__ out)
{
    extern __shared__ float sm[];
    float* xs   = sm + OFF_XS;
    float* hs   = sm + OFF_HS;
    float* wdw  = sm + OFF_WDW;
    float* lnw  = sm + OFF_LNW;
    float* lnb  = sm + OFF_LNB;
    float* win  = sm + OFF_WIN;
    float* bin  = sm + OFF_BIN;
    float* wout = sm + OFF_WOUT;
    float* bout = sm + OFF_BOUT;
    float* red  = sm + OFF_RED;
    float* stat = sm + OFF_STAT;

    int unit = blockIdx.x;
    int n = unit >> 3, l = unit & 7;
    int b = n >> 8, rem = n & 255, ph = rem >> 4, pw_ = rem & 15;
    const size_t cstride = (size_t)LDEP * PLANE;
    const float* xbase = x + ((size_t)b * CCH * LDEP + l) * PLANE
                           + (ph * 8) * 128 + pw_ * 8;
    int t = threadIdx.x;

    // ---- load x tile ----
    for (int i = t; i < 4096; i += 256) {
        int c = i >> 6, j = i & 63, p = (j >> 3), q = j & 7;
        xs[c * 68 + j] = xbase[(size_t)c * cstride + p * 128 + q];
    }

    int2   ei = g_topi[n];
    float2 ew = g_topw[n];

    int c_ = t & 63, k4 = t >> 6;     // conv/LN mapping (k4 warp-uniform)
    int jt = t & 15, ot = t >> 4;     // gemm mapping
    int j0 = jt * 4;

    __syncthreads();

    // residual in registers (vectorized reads)
    float oacc[4][4];
    #pragma unroll
    for (int m = 0; m < 4; ++m) {
        float4 v = *(const float4*)(xs + (ot + m * 16) * 68 + j0);
        oacc[m][0] = v.x; oacc[m][1] = v.y; oacc[m][2] = v.z; oacc[m][3] = v.w;
    }

    for (int kk = 0; kk < 2; ++kk) {
        int   e    = kk ? ei.y : ei.x;
        float wexp = kk ? ew.y : ew.x;

        __syncthreads();  // prior-expert reads of weights/hs done

        // ---- stage expert weights ----
        {
            const float* g = dw_w + (size_t)e * 3136;
            for (int i = t; i < 3136; i += 256) wdw[i] = g[i];
            if (t < 64) { lnw[t] = ln_w[e * 64 + t]; lnb[t] = ln_b[e * 64 + t]; }
            const float* gi = pw_in_w + (size_t)e * 8192;
            for (int i = t; i < 8192; i += 256) {
                int o = i >> 6, c = i & 63;
                win[o * 68 + c] = gi[i];
            }
            if (t < 128) bin[t] = pw_in_b[e * 128 + t];
            const float* go = pw_out_w + (size_t)e * 4096;
            for (int i = t; i < 4096; i += 256) {
                int o = i >> 6, c = i & 63;
                wout[o * 68 + c] = go[i];
            }
            if (t < 64) bout[t] = pw_out_b[e * 64 + t];
        }
        __syncthreads();

        // ---- depthwise conv, register-tiled; k4 warp-uniform dispatch ----
        // (dw_b constant per channel -> cancels exactly in the LayerNorm)
        float hv[16];
        {
            const float* xr = xs + c_ * 68;
            const float* wr = wdw + c_ * 49;
            switch (k4) {
                case 0: conv_pair<0>(xr, wr, hv); break;
                case 1: conv_pair<2>(xr, wr, hv); break;
                case 2: conv_pair<4>(xr, wr, hv); break;
                default: conv_pair<6>(xr, wr, hv); break;
            }
        }

        // ---- LayerNorm over 64 spatial positions per channel ----
        {
            float s = 0.f, sq = 0.f;
            #pragma unroll
            for (int jj = 0; jj < 16; ++jj) { s += hv[jj]; sq += hv[jj] * hv[jj]; }
            red[t] = s; red[256 + t] = sq;
        }
        __syncthreads();
        if (t < 64) {
            float S = red[t] + red[t + 64] + red[t + 128] + red[t + 192];
            float Q = red[256 + t] + red[320 + t] + red[384 + t] + red[448 + t];
            float mu  = S * (1.f / 64.f);
            float var = fmaxf(Q * (1.f / 64.f) - mu * mu, 0.f);
            stat[t]      = mu;
            stat[64 + t] = rsqrtf(var + EPS);
        }
        __syncthreads();
        {
            float mu = stat[c_], rs = stat[64 + c_];
            float* hrow = hs + c_ * 68 + k4 * 16;
            #pragma unroll
            for (int v = 0; v < 4; ++v) {
                int j = k4 * 16 + v * 4;
                float4 o4;
                o4.x = (hv[v*4+0] - mu) * rs * lnw[j+0] + lnb[j+0];
                o4.y = (hv[v*4+1] - mu) * rs * lnw[j+1] + lnb[j+1];
                o4.z = (hv[v*4+2] - mu) * rs * lnw[j+2] + lnb[j+2];
                o4.w = (hv[v*4+3] - mu) * rs * lnw[j+3] + lnb[j+3];
                *(float4*)(hrow + v * 4) = o4;
            }
        }
        __syncthreads();

        // ---- pw_in: [128,64] @ [64,64pos], vectorized weight loads ----
        float fa[4][4] = {}, fg[4][4] = {};
        #pragma unroll 4
        for (int c0 = 0; c0 < 64; c0 += 4) {
            float4 h0 = *(const float4*)(hs + (c0 + 0) * 68 + j0);
            float4 h1 = *(const float4*)(hs + (c0 + 1) * 68 + j0);
            float4 h2 = *(const float4*)(hs + (c0 + 2) * 68 + j0);
            float4 h3 = *(const float4*)(hs + (c0 + 3) * 68 + j0);
            #pragma unroll
            for (int m = 0; m < 4; ++m) {
                int oa = ot + m * 16;
                float4 wa = *(const float4*)(win + oa * 68 + c0);
                float4 wg = *(const float4*)(win + (oa + 64) * 68 + c0);
                ACC4(fa[m], wa.x, h0); ACC4(fa[m], wa.y, h1);
                ACC4(fa[m], wa.z, h2); ACC4(fa[m], wa.w, h3);
                ACC4(fg[m], wg.x, h0); ACC4(fg[m], wg.y, h1);
                ACC4(fg[m], wg.z, h2); ACC4(fg[m], wg.w, h3);
            }
        }
        __syncthreads();  // all reads of hs finished

        // ---- gate: silu(a) * g, write back into hs ----
        #pragma unroll
        for (int m = 0; m < 4; ++m) {
            int oa = ot + m * 16;
            float ba = bin[oa], bg = bin[oa + 64];
            float4 gv;
            {
                float a = fa[m][0] + ba, g = fg[m][0] + bg;
                gv.x = a * g * __fdividef(1.f, 1.f + __expf(-a));
                a = fa[m][1] + ba; g = fg[m][1] + bg;
                gv.y = a * g * __fdividef(1.f, 1.f + __expf(-a));
                a = fa[m][2] + ba; g = fg[m][2] + bg;
                gv.z = a * g * __fdividef(1.f, 1.f + __expf(-a));
                a = fa[m][3] + ba; g = fg[m][3] + bg;
                gv.w = a * g * __fdividef(1.f, 1.f + __expf(-a));
            }
            *(float4*)(hs + oa * 68 + j0) = gv;
        }
        __syncthreads();

        // ---- pw_out: [64,64] @ [64,64pos], vectorized weight loads ----
        float ro[4][4] = {};
        #pragma unroll 4
        for (int c0 = 0; c0 < 64; c0 += 4) {
            float4 h0 = *(const float4*)(hs + (c0 + 0) * 68 + j0);
            float4 h1 = *(const float4*)(hs + (c0 + 1) * 68 + j0);
            float4 h2 = *(const float4*)(hs + (c0 + 2) * 68 + j0);
            float4 h3 = *(const float4*)(hs + (c0 + 3) * 68 + j0);
            #pragma unroll
            for (int m = 0; m < 4; ++m) {
                float4 w4 = *(const float4*)(wout + (ot + m * 16) * 68 + c0);
                ACC4(ro[m], w4.x, h0); ACC4(ro[m], w4.y, h1);
                ACC4(ro[m], w4.z, h2); ACC4(ro[m], w4.w, h3);
            }
        }
        #pragma unroll
        for (int m = 0; m < 4; ++m) {
            float bo = bout[ot + m * 16];
            #pragma unroll
            for (int r = 0; r < 4; ++r)
                oacc[m][r] = fmaf(wexp, ro[m][r] + bo, oacc[m][r]);
        }
    }

    // ---- write out ----
    float* obase = out + ((size_t)b * CCH * LDEP + l) * PLANE
                       + (ph * 8) * 128 + pw_ * 8;
    int p = j0 >> 3, q = j0 & 7;
    #pragma unroll
    for (int m = 0; m < 4; ++m) {
        int o = ot + m * 16;
        float4 v = make_float4(oacc[m][0], oacc[m][1], oacc[m][2], oacc[m][3]);
        *(float4*)(obase + (size_t)o * cstride + p * 128 + q) = v;
    }
}

// ---------------------------------------------------------------------------
extern "C" void kernel_launch(void* const* d_in, const int* in_sizes, int n_in,
                              void* d_out, int out_size)
{
    const float* x        = (const float*)d_in[0];
    const float* router_w = (const float*)d_in[1];
    const float* router_b = (const float*)d_in[2];
    const float* dw_w     = (const float*)d_in[3];
    // d_in[4] = dw_b: constant per channel, cancels through LayerNorm
    const float* ln_w     = (const float*)d_in[5];
    const float* ln_b     = (const float*)d_in[6];
    const float* pw_in_w  = (const float*)d_in[7];
    const float* pw_in_b  = (const float*)d_in[8];
    const float* pw_out_w = (const float*)d_in[9];
    const float* pw_out_b = (const float*)d_in[10];
    float* out = (float*)d_out;

    cudaFuncSetAttribute(moe_kernel,
                         cudaFuncAttributeMaxDynamicSharedMemorySize,
                         SMEM_BYTES);

    router_kernel<<<NPATCH, 256>>>(x, router_w, router_b);
    moe_kernel<<<NPATCH * LDEP, 256, SMEM_BYTES>>>(
        x, dw_w, ln_w, ln_b, pw_in_w, pw_in_b, pw_out_w, pw_out_b, out);
}